// round 5
// baseline (speedup 1.0000x reference)
#include <cuda_runtime.h>
#include <cstdint>

#define NN 100000
#define EE 1600000
#define FULLMASK 0xffffffffu

// Scratch: projection planes [4][N][64] (q,k,v,skip), CSR row pointers,
// per-edge score/weight spill buffer (only used for rare deg>32 nodes).
__device__ float g_proj[(size_t)4 * NN * 64];     // 102.4 MB
__device__ float g_scores[(size_t)EE * 4];        // 25.6 MB (slow path only)
__device__ int   g_rowptr[NN + 1];

// ---------------------------------------------------------------------------
// K0: row_ptr[n] = lower_bound(edge_dst, n). edge_dst is sorted.
// ---------------------------------------------------------------------------
__global__ void rowptr_kernel(const int* __restrict__ edst) {
    int n = blockIdx.x * blockDim.x + threadIdx.x;
    if (n > NN) return;
    int lo = 0, hi = EE;
    while (lo < hi) {
        int mid = (lo + hi) >> 1;
        if (edst[mid] < n) lo = mid + 1; else hi = mid;
    }
    g_rowptr[n] = lo;
}

// ---------------------------------------------------------------------------
// K1: fused projection GEMM.  proj[p][n][c] = feat[n] @ W_p[:,c] + b_p[c]
// ---------------------------------------------------------------------------
__global__ void __launch_bounds__(256, 2) proj_kernel(
    const float* __restrict__ feat,
    const float* __restrict__ Wq, const float* __restrict__ bq,
    const float* __restrict__ Wk, const float* __restrict__ bk,
    const float* __restrict__ Wv, const float* __restrict__ bv,
    const float* __restrict__ Ws, const float* __restrict__ bs)
{
    __shared__ float fs[8][64];
    const int tid = threadIdx.x;
    const int p = tid >> 6, col = tid & 63;
    const float* W = (p == 0) ? Wq : (p == 1) ? Wk : (p == 2) ? Wv : Ws;
    const float* B = (p == 0) ? bq : (p == 1) ? bk : (p == 2) ? bv : bs;

    float w[64];
#pragma unroll
    for (int k = 0; k < 64; k++) w[k] = W[k * 64 + col];
    const float bias = B[col];
    float* out = g_proj + (size_t)p * NN * 64;

    const int row0 = blockIdx.x * 256;
    for (int it = 0; it < 32; it++) {
        const int rbase = row0 + it * 8;
        if (rbase >= NN) break;
        __syncthreads();
        for (int idx = tid; idx < 512; idx += 256) {
            int r = rbase + (idx >> 6);
            fs[idx >> 6][idx & 63] = (r < NN) ? feat[(size_t)r * 64 + (idx & 63)] : 0.f;
        }
        __syncthreads();
        float acc[8];
#pragma unroll
        for (int r = 0; r < 8; r++) acc[r] = bias;
#pragma unroll
        for (int k = 0; k < 64; k++) {
            const float wv = w[k];
#pragma unroll
            for (int r = 0; r < 8; r++) acc[r] += wv * fs[r][k];
        }
#pragma unroll
        for (int r = 0; r < 8; r++) {
            int row = rbase + r;
            if (row < NN) out[(size_t)row * 64 + col] = acc[r];
        }
    }
}

// ---------------------------------------------------------------------------
// K2 (fused): one warp per destination node.
//  - k[dst] row staged in smem once per node (no per-edge k gather)
//  - Phase 1 (lane-parallel, lane=edge): gather q[src] row, dot -> 4 scores
//  - warp softmax (max-reduce, exp, sum-reduce), weights staged in smem
//  - Phase 2 (serial over edges): broadcast LDS weight + coalesced v gather
//  - Epilogue: gated skip, LayerNorm, PReLU
//  deg>32 nodes (rare) spill scores/weights through g_scores.
// ---------------------------------------------------------------------------
__global__ void __launch_bounds__(256) agg_fused_kernel(
    const int* __restrict__ esrc,
    const float* __restrict__ Wg, const float* __restrict__ bg,
    const float* __restrict__ ln_g, const float* __restrict__ ln_b,
    const float* __restrict__ prelu_a,
    float* __restrict__ out)
{
    __shared__ float ks[8][64];
    __shared__ float4 wts[8][32];

    const int wip  = threadIdx.x >> 5;                       // warp in block
    const int lane = threadIdx.x & 31;
    const int node = blockIdx.x * 8 + wip;
    if (node >= NN) return;

    const int beg = g_rowptr[node], end = g_rowptr[node + 1];
    const int deg = end - beg;

    const float* qplane = g_proj;
    const float* kplane = g_proj + (size_t)1 * NN * 64;
    const float* vplane = g_proj + (size_t)2 * NN * 64;
    const float* splane = g_proj + (size_t)3 * NN * 64;

    // stage k[node] row in smem
    ks[wip][lane]      = kplane[(size_t)node * 64 + lane];
    ks[wip][lane + 32] = kplane[(size_t)node * 64 + lane + 32];
    __syncwarp();
    const float4* kf = (const float4*)ks[wip];

    float m[4], inv[4];

    if (deg <= 32) {
        // ---- fast path: all scores live in registers ----
        const int e = beg + lane;
        const bool valid = (e < end);
        float sc[4] = {-3e38f, -3e38f, -3e38f, -3e38f};
        if (valid) {
            const int src = esrc[e];
            const float4* qr = (const float4*)(qplane + (size_t)src * 64);
            float a[4] = {0.f, 0.f, 0.f, 0.f};
#pragma unroll
            for (int i = 0; i < 16; i++) {
                float4 qv = qr[i], kv = kf[i];
                a[i >> 2] += qv.x * kv.x + qv.y * kv.y + qv.z * kv.z + qv.w * kv.w;
            }
#pragma unroll
            for (int h = 0; h < 4; h++) sc[h] = a[h] * 0.25f;
        }
        // warp max
#pragma unroll
        for (int h = 0; h < 4; h++) m[h] = sc[h];
#pragma unroll
        for (int off = 16; off; off >>= 1)
#pragma unroll
            for (int h = 0; h < 4; h++)
                m[h] = fmaxf(m[h], __shfl_xor_sync(FULLMASK, m[h], off));
        // exp + warp sum
        float w[4], s[4];
#pragma unroll
        for (int h = 0; h < 4; h++) { w[h] = valid ? __expf(sc[h] - m[h]) : 0.f; s[h] = w[h]; }
#pragma unroll
        for (int off = 16; off; off >>= 1)
#pragma unroll
            for (int h = 0; h < 4; h++)
                s[h] += __shfl_xor_sync(FULLMASK, s[h], off);
#pragma unroll
        for (int h = 0; h < 4; h++) inv[h] = (s[h] > 0.f) ? 1.f / s[h] : 0.f;
        if (valid)
            wts[wip][lane] = make_float4(w[0] * inv[0], w[1] * inv[1], w[2] * inv[2], w[3] * inv[3]);
        __syncwarp();
    } else {
        // ---- slow path: chunked through g_scores ----
        float mloc[4] = {-3e38f, -3e38f, -3e38f, -3e38f};
        for (int c = beg; c < end; c += 32) {
            const int e = c + lane;
            if (e < end) {
                const int src = esrc[e];
                const float4* qr = (const float4*)(qplane + (size_t)src * 64);
                float a[4] = {0.f, 0.f, 0.f, 0.f};
#pragma unroll
                for (int i = 0; i < 16; i++) {
                    float4 qv = qr[i], kv = kf[i];
                    a[i >> 2] += qv.x * kv.x + qv.y * kv.y + qv.z * kv.z + qv.w * kv.w;
                }
                float4 scv = make_float4(a[0] * 0.25f, a[1] * 0.25f, a[2] * 0.25f, a[3] * 0.25f);
                *(float4*)(g_scores + (size_t)e * 4) = scv;
                mloc[0] = fmaxf(mloc[0], scv.x); mloc[1] = fmaxf(mloc[1], scv.y);
                mloc[2] = fmaxf(mloc[2], scv.z); mloc[3] = fmaxf(mloc[3], scv.w);
            }
        }
#pragma unroll
        for (int off = 16; off; off >>= 1)
#pragma unroll
            for (int h = 0; h < 4; h++)
                mloc[h] = fmaxf(mloc[h], __shfl_xor_sync(FULLMASK, mloc[h], off));
#pragma unroll
        for (int h = 0; h < 4; h++) m[h] = mloc[h];

        float sloc[4] = {0.f, 0.f, 0.f, 0.f};
        for (int c = beg; c < end; c += 32) {
            const int e = c + lane;
            if (e < end) {
                float4 scv = *(const float4*)(g_scores + (size_t)e * 4);
                float4 wv = make_float4(__expf(scv.x - m[0]), __expf(scv.y - m[1]),
                                        __expf(scv.z - m[2]), __expf(scv.w - m[3]));
                *(float4*)(g_scores + (size_t)e * 4) = wv;
                sloc[0] += wv.x; sloc[1] += wv.y; sloc[2] += wv.z; sloc[3] += wv.w;
            }
        }
#pragma unroll
        for (int off = 16; off; off >>= 1)
#pragma unroll
            for (int h = 0; h < 4; h++)
                sloc[h] += __shfl_xor_sync(FULLMASK, sloc[h], off);
#pragma unroll
        for (int h = 0; h < 4; h++) inv[h] = (sloc[h] > 0.f) ? 1.f / sloc[h] : 0.f;
    }

    // ---- phase 2: weighted aggregation (serial over node's edges) ----
    const bool lowh = (lane < 16);
    float acc0 = 0.f, acc1 = 0.f;

    if (deg <= 32) {
        for (int j = 0; j < deg; j++) {
            float4 wt = wts[wip][j];                 // broadcast LDS
            const int src = esrc[beg + j];           // broadcast
            const float* vr = vplane + (size_t)src * 64;
            const float wA = lowh ? wt.x : wt.y;
            const float wB = lowh ? wt.z : wt.w;
            acc0 += wA * vr[lane];
            acc1 += wB * vr[lane + 32];
        }
    } else {
        for (int c = beg; c < end; c += 32) {
            const int e = c + lane;
            if (e < end) {
                float4 wv = *(const float4*)(g_scores + (size_t)e * 4);
                wts[wip][lane] = make_float4(wv.x * inv[0], wv.y * inv[1],
                                             wv.z * inv[2], wv.w * inv[3]);
            }
            __syncwarp();
            const int cnt = min(32, end - c);
            for (int j = 0; j < cnt; j++) {
                float4 wt = wts[wip][j];
                const int src = esrc[c + j];
                const float* vr = vplane + (size_t)src * 64;
                const float wA = lowh ? wt.x : wt.y;
                const float wB = lowh ? wt.z : wt.w;
                acc0 += wA * vr[lane];
                acc1 += wB * vr[lane + 32];
            }
            __syncwarp();
        }
    }

    // ---- gated skip ----
    const float sk0 = splane[(size_t)node * 64 + lane];
    const float sk1 = splane[(size_t)node * 64 + lane + 32];
    float gp = sk0 * Wg[lane]      + acc0 * Wg[64 + lane] + (sk0 - acc0) * Wg[128 + lane]
             + sk1 * Wg[lane + 32] + acc1 * Wg[96 + lane] + (sk1 - acc1) * Wg[160 + lane];
#pragma unroll
    for (int off = 16; off; off >>= 1) gp += __shfl_xor_sync(FULLMASK, gp, off);
    const float gate = 1.f / (1.f + __expf(-(gp + bg[0])));
    const float r0 = gate * sk0 + (1.f - gate) * acc0;
    const float r1 = gate * sk1 + (1.f - gate) * acc1;

    // ---- LayerNorm over 64 dims ----
    float sum = r0 + r1, sq = r0 * r0 + r1 * r1;
#pragma unroll
    for (int off = 16; off; off >>= 1) {
        sum += __shfl_xor_sync(FULLMASK, sum, off);
        sq  += __shfl_xor_sync(FULLMASK, sq,  off);
    }
    const float mu = sum * (1.f / 64.f);
    const float var = sq * (1.f / 64.f) - mu * mu;
    const float rstd = rsqrtf(var + 1e-5f);
    const float a = prelu_a[0];

    float o0 = (r0 - mu) * rstd * ln_g[lane]      + ln_b[lane];
    float o1 = (r1 - mu) * rstd * ln_g[lane + 32] + ln_b[lane + 32];
    o0 = (o0 >= 0.f) ? o0 : a * o0;
    o1 = (o1 >= 0.f) ? o1 : a * o1;
    out[(size_t)node * 64 + lane]      = o0;
    out[(size_t)node * 64 + lane + 32] = o1;
}

// ---------------------------------------------------------------------------
extern "C" void kernel_launch(void* const* d_in, const int* in_sizes, int n_in,
                              void* d_out, int out_size)
{
    const float* feat    = (const float*)d_in[0];
    const int*   esrc    = (const int*)  d_in[1];
    const int*   edst    = (const int*)  d_in[2];
    const float* Wq      = (const float*)d_in[3];
    const float* bq      = (const float*)d_in[4];
    const float* Wk      = (const float*)d_in[5];
    const float* bk      = (const float*)d_in[6];
    const float* Wv      = (const float*)d_in[7];
    const float* bv      = (const float*)d_in[8];
    const float* Ws      = (const float*)d_in[9];
    const float* bs      = (const float*)d_in[10];
    const float* Wg      = (const float*)d_in[11];
    const float* bg      = (const float*)d_in[12];
    const float* ln_g    = (const float*)d_in[13];
    const float* ln_b    = (const float*)d_in[14];
    const float* prelu_a = (const float*)d_in[15];
    float* out = (float*)d_out;

    rowptr_kernel<<<(NN + 1 + 255) / 256, 256>>>(edst);
    proj_kernel<<<(NN + 255) / 256, 256>>>(feat, Wq, bq, Wk, bk, Wv, bv, Ws, bs);
    agg_fused_kernel<<<(NN + 7) / 8, 256>>>(esrc, Wg, bg, ln_g, ln_b, prelu_a, out);
}

// round 8
// speedup vs baseline: 1.1017x; 1.1017x over previous
#include <cuda_runtime.h>
#include <cstdint>

#define NN 100000
#define EE 1600000
#define FULLMASK 0xffffffffu

// Scratch: projection planes [4][N][64] (q,k,v,skip), slow-path spill.
__device__ float g_proj[(size_t)4 * NN * 64];     // 102.4 MB
__device__ float g_scores[(size_t)EE * 4];        // 25.6 MB (deg>32 only)

// ---------------------------------------------------------------------------
// K1: projection GEMM, 8x8 register tiling.
// Block computes 128 rows x 128 cols (one plane pair: y=0 -> {q,k}, y=1 -> {v,s}).
// feat tile transposed into smem. Pad = 132 (multiple of 4) so float4 row
// loads stay 16B-aligned; compute loads are broadcast so no conflicts.
// ---------------------------------------------------------------------------
__global__ void __launch_bounds__(256) proj_kernel(
    const float* __restrict__ feat,
    const float* __restrict__ Wq, const float* __restrict__ bq,
    const float* __restrict__ Wk, const float* __restrict__ bk,
    const float* __restrict__ Wv, const float* __restrict__ bv,
    const float* __restrict__ Ws, const float* __restrict__ bs)
{
    __shared__ float a_t[32][132];   // [k][row], pad 132 keeps float4 aligned
    __shared__ float b_t[32][128];   // [k][col]  (col<64 -> plane A, else B)

    const int tid = threadIdx.x;
    const int rbase = blockIdx.x * 128;
    const int pp = blockIdx.y;                       // 0:{q,k} 1:{v,s}
    const float* WA = pp ? Wv : Wq;
    const float* WB = pp ? Ws : Wk;
    const float* bA = pp ? bv : bq;
    const float* bB = pp ? bs : bk;

    const int tx = tid & 15, ty = tid >> 4;
    const int col0 = tx * 8;                         // 0..120 (one plane only)
    const int row0 = ty * 8;                         // local row

    float acc[8][8];
    {
        const float* bb = (col0 < 64) ? bA : bB;
        const int c0 = col0 & 63;
#pragma unroll
        for (int j = 0; j < 8; j++) {
            const float b = bb[c0 + j];
#pragma unroll
            for (int i = 0; i < 8; i++) acc[i][j] = b;
        }
    }

    for (int kb = 0; kb < 64; kb += 32) {
        __syncthreads();
        // load feat tile transposed: 4096 elems, 16 passes
#pragma unroll
        for (int p = 0; p < 16; p++) {
            const int idx = p * 256 + tid;
            const int row = idx >> 5, k = idx & 31;
            const int grow = rbase + row;
            a_t[k][row] = (grow < NN) ? feat[(size_t)grow * 64 + kb + k] : 0.f;
        }
        // load W tile: b_t[k][c]
#pragma unroll
        for (int p = 0; p < 16; p++) {
            const int idx = p * 256 + tid;
            const int k = idx >> 7, c = idx & 127;
            const float* W = (c < 64) ? WA : WB;
            b_t[k][c] = W[(size_t)(kb + k) * 64 + (c & 63)];
        }
        __syncthreads();

#pragma unroll
        for (int k = 0; k < 32; k++) {
            float a[8], b[8];
            *(float4*)&a[0] = *(const float4*)&a_t[k][row0];
            *(float4*)&a[4] = *(const float4*)&a_t[k][row0 + 4];
            *(float4*)&b[0] = *(const float4*)&b_t[k][col0];
            *(float4*)&b[4] = *(const float4*)&b_t[k][col0 + 4];
#pragma unroll
            for (int i = 0; i < 8; i++)
#pragma unroll
                for (int j = 0; j < 8; j++)
                    acc[i][j] += a[i] * b[j];
        }
    }

    // epilogue
    const int plane = pp * 2 + (col0 >= 64);
    float* out = g_proj + (size_t)plane * NN * 64 + (col0 & 63);
#pragma unroll
    for (int i = 0; i < 8; i++) {
        const int grow = rbase + row0 + i;
        if (grow < NN) {
            float* o = out + (size_t)grow * 64;
            *(float4*)o       = make_float4(acc[i][0], acc[i][1], acc[i][2], acc[i][3]);
            *(float4*)(o + 4) = make_float4(acc[i][4], acc[i][5], acc[i][6], acc[i][7]);
        }
    }
}

// ---------------------------------------------------------------------------
// K2 (fused): one warp per destination node. Inline CSR bounds (binary search
// on sorted edge_dst by lanes 0/1). Phase 1: 4 lanes per edge (lane&3 = head),
// coalesced q gathers, per-lane 16-dim dot, scores staged in smem. Warp
// softmax. Phase 2: serial edge loop, broadcast smem weight/src + coalesced v.
// Epilogue: gated skip, LayerNorm, PReLU. deg>32 spills through g_scores.
// ---------------------------------------------------------------------------
__global__ void __launch_bounds__(256) agg_fused_kernel(
    const int* __restrict__ esrc,
    const int* __restrict__ edst,
    const float* __restrict__ Wg, const float* __restrict__ bg,
    const float* __restrict__ ln_g, const float* __restrict__ ln_b,
    const float* __restrict__ prelu_a,
    float* __restrict__ out)
{
    __shared__ float  ks[8][64];
    __shared__ float4 wts[8][32];    // raw scores then normalized weights
    __shared__ int    srcs[8][32];

    const int wip  = threadIdx.x >> 5;
    const int lane = threadIdx.x & 31;
    const int node = blockIdx.x * 8 + wip;
    if (node >= NN) return;

    // inline rowptr: lanes 0/1 search lower_bound(node), lower_bound(node+1)
    int sres = 0;
    if (lane < 2) {
        const int target = node + lane;
        int lo = 0, hi = EE;
        while (lo < hi) {
            int mid = (lo + hi) >> 1;
            if (edst[mid] < target) lo = mid + 1; else hi = mid;
        }
        sres = lo;
    }
    const int beg = __shfl_sync(FULLMASK, sres, 0);
    const int end = __shfl_sync(FULLMASK, sres, 1);
    const int deg = end - beg;

    const float* qplane = g_proj;
    const float* kplane = g_proj + (size_t)1 * NN * 64;
    const float* vplane = g_proj + (size_t)2 * NN * 64;
    const float* splane = g_proj + (size_t)3 * NN * 64;

    // stage k[node]
    ks[wip][lane]      = kplane[(size_t)node * 64 + lane];
    ks[wip][lane + 32] = kplane[(size_t)node * 64 + lane + 32];
    __syncwarp();

    float inv[4];

    if (deg <= 32) {
        // ---- phase 1: 4 lanes per edge, 8 edges per iteration ----
        const int h = lane & 3;
        const float4* kr = (const float4*)(ks[wip] + h * 16);
        const float4 k0 = kr[0], k1 = kr[1], k2 = kr[2], k3 = kr[3];
        const int nIter = (deg + 7) >> 3;
        for (int it = 0; it < nIter; it++) {
            const int eidx = it * 8 + (lane >> 2);
            if (eidx < deg) {
                const int src = esrc[beg + eidx];
                const float4* qr = (const float4*)(qplane + (size_t)src * 64 + h * 16);
                const float4 q0 = qr[0], q1 = qr[1], q2 = qr[2], q3 = qr[3];
                float d = q0.x*k0.x + q0.y*k0.y + q0.z*k0.z + q0.w*k0.w
                        + q1.x*k1.x + q1.y*k1.y + q1.z*k1.z + q1.w*k1.w
                        + q2.x*k2.x + q2.y*k2.y + q2.z*k2.z + q2.w*k2.w
                        + q3.x*k3.x + q3.y*k3.y + q3.z*k3.z + q3.w*k3.w;
                ((float*)wts[wip])[eidx * 4 + h] = d * 0.25f;
                if (h == 0) srcs[wip][eidx] = src;
            }
        }
        __syncwarp();

        // ---- softmax over deg edges, per head ----
        const bool valid = (lane < deg);
        float4 sc = valid ? wts[wip][lane]
                          : make_float4(-3e38f, -3e38f, -3e38f, -3e38f);
        float m0 = sc.x, m1 = sc.y, m2 = sc.z, m3 = sc.w;
#pragma unroll
        for (int off = 16; off; off >>= 1) {
            m0 = fmaxf(m0, __shfl_xor_sync(FULLMASK, m0, off));
            m1 = fmaxf(m1, __shfl_xor_sync(FULLMASK, m1, off));
            m2 = fmaxf(m2, __shfl_xor_sync(FULLMASK, m2, off));
            m3 = fmaxf(m3, __shfl_xor_sync(FULLMASK, m3, off));
        }
        float w0 = valid ? __expf(sc.x - m0) : 0.f;
        float w1 = valid ? __expf(sc.y - m1) : 0.f;
        float w2 = valid ? __expf(sc.z - m2) : 0.f;
        float w3 = valid ? __expf(sc.w - m3) : 0.f;
        float s0 = w0, s1 = w1, s2 = w2, s3 = w3;
#pragma unroll
        for (int off = 16; off; off >>= 1) {
            s0 += __shfl_xor_sync(FULLMASK, s0, off);
            s1 += __shfl_xor_sync(FULLMASK, s1, off);
            s2 += __shfl_xor_sync(FULLMASK, s2, off);
            s3 += __shfl_xor_sync(FULLMASK, s3, off);
        }
        const float i0 = (s0 > 0.f) ? 1.f / s0 : 0.f;
        const float i1 = (s1 > 0.f) ? 1.f / s1 : 0.f;
        const float i2 = (s2 > 0.f) ? 1.f / s2 : 0.f;
        const float i3 = (s3 > 0.f) ? 1.f / s3 : 0.f;
        if (valid)
            wts[wip][lane] = make_float4(w0 * i0, w1 * i1, w2 * i2, w3 * i3);
        __syncwarp();
    } else {
        // ---- slow path (rare): chunked through g_scores ----
        const float4* kf = (const float4*)ks[wip];
        float mloc[4] = {-3e38f, -3e38f, -3e38f, -3e38f};
        for (int c = beg; c < end; c += 32) {
            const int e = c + lane;
            if (e < end) {
                const int src = esrc[e];
                const float4* qr = (const float4*)(qplane + (size_t)src * 64);
                float a[4] = {0.f, 0.f, 0.f, 0.f};
#pragma unroll
                for (int i = 0; i < 16; i++) {
                    float4 qv = qr[i], kv = kf[i];
                    a[i >> 2] += qv.x * kv.x + qv.y * kv.y + qv.z * kv.z + qv.w * kv.w;
                }
                float4 scv = make_float4(a[0] * 0.25f, a[1] * 0.25f, a[2] * 0.25f, a[3] * 0.25f);
                *(float4*)(g_scores + (size_t)e * 4) = scv;
                mloc[0] = fmaxf(mloc[0], scv.x); mloc[1] = fmaxf(mloc[1], scv.y);
                mloc[2] = fmaxf(mloc[2], scv.z); mloc[3] = fmaxf(mloc[3], scv.w);
            }
        }
#pragma unroll
        for (int off = 16; off; off >>= 1)
#pragma unroll
            for (int h = 0; h < 4; h++)
                mloc[h] = fmaxf(mloc[h], __shfl_xor_sync(FULLMASK, mloc[h], off));
        float sloc[4] = {0.f, 0.f, 0.f, 0.f};
        for (int c = beg; c < end; c += 32) {
            const int e = c + lane;
            if (e < end) {
                float4 scv = *(const float4*)(g_scores + (size_t)e * 4);
                float4 wv = make_float4(__expf(scv.x - mloc[0]), __expf(scv.y - mloc[1]),
                                        __expf(scv.z - mloc[2]), __expf(scv.w - mloc[3]));
                *(float4*)(g_scores + (size_t)e * 4) = wv;
                sloc[0] += wv.x; sloc[1] += wv.y; sloc[2] += wv.z; sloc[3] += wv.w;
            }
        }
#pragma unroll
        for (int off = 16; off; off >>= 1)
#pragma unroll
            for (int h = 0; h < 4; h++)
                sloc[h] += __shfl_xor_sync(FULLMASK, sloc[h], off);
#pragma unroll
        for (int h = 0; h < 4; h++)
            inv[h] = (sloc[h] > 0.f) ? 1.f / sloc[h] : 0.f;
    }

    // ---- phase 2: weighted aggregation ----
    const bool lowh = (lane < 16);
    float acc0 = 0.f, acc1 = 0.f;

    if (deg <= 32) {
        for (int j = 0; j < deg; j++) {
            const float4 wt = wts[wip][j];          // broadcast LDS.128
            const int src = srcs[wip][j];           // broadcast LDS
            const float* vr = vplane + (size_t)src * 64;
            const float wA = lowh ? wt.x : wt.y;
            const float wB = lowh ? wt.z : wt.w;
            acc0 += wA * vr[lane];
            acc1 += wB * vr[lane + 32];
        }
    } else {
        for (int c = beg; c < end; c += 32) {
            const int e = c + lane;
            if (e < end) {
                float4 wv = *(const float4*)(g_scores + (size_t)e * 4);
                wts[wip][lane] = make_float4(wv.x * inv[0], wv.y * inv[1],
                                             wv.z * inv[2], wv.w * inv[3]);
            }
            __syncwarp();
            const int cnt = min(32, end - c);
            for (int j = 0; j < cnt; j++) {
                const float4 wt = wts[wip][j];
                const int src = esrc[c + j];
                const float* vr = vplane + (size_t)src * 64;
                const float wA = lowh ? wt.x : wt.y;
                const float wB = lowh ? wt.z : wt.w;
                acc0 += wA * vr[lane];
                acc1 += wB * vr[lane + 32];
            }
            __syncwarp();
        }
    }

    // ---- gated skip ----
    const float sk0 = splane[(size_t)node * 64 + lane];
    const float sk1 = splane[(size_t)node * 64 + lane + 32];
    float gp = sk0 * Wg[lane]      + acc0 * Wg[64 + lane] + (sk0 - acc0) * Wg[128 + lane]
             + sk1 * Wg[lane + 32] + acc1 * Wg[96 + lane] + (sk1 - acc1) * Wg[160 + lane];
#pragma unroll
    for (int off = 16; off; off >>= 1) gp += __shfl_xor_sync(FULLMASK, gp, off);
    const float gate = 1.f / (1.f + __expf(-(gp + bg[0])));
    const float r0 = gate * sk0 + (1.f - gate) * acc0;
    const float r1 = gate * sk1 + (1.f - gate) * acc1;

    // ---- LayerNorm over 64 dims + PReLU ----
    float sum = r0 + r1, sq = r0 * r0 + r1 * r1;
#pragma unroll
    for (int off = 16; off; off >>= 1) {
        sum += __shfl_xor_sync(FULLMASK, sum, off);
        sq  += __shfl_xor_sync(FULLMASK, sq,  off);
    }
    const float mu = sum * (1.f / 64.f);
    const float var = sq * (1.f / 64.f) - mu * mu;
    const float rstd = rsqrtf(var + 1e-5f);
    const float a = prelu_a[0];

    float o0 = (r0 - mu) * rstd * ln_g[lane]      + ln_b[lane];
    float o1 = (r1 - mu) * rstd * ln_g[lane + 32] + ln_b[lane + 32];
    o0 = (o0 >= 0.f) ? o0 : a * o0;
    o1 = (o1 >= 0.f) ? o1 : a * o1;
    out[(size_t)node * 64 + lane]      = o0;
    out[(size_t)node * 64 + lane + 32] = o1;
}

// ---------------------------------------------------------------------------
extern "C" void kernel_launch(void* const* d_in, const int* in_sizes, int n_in,
                              void* d_out, int out_size)
{
    const float* feat    = (const float*)d_in[0];
    const int*   esrc    = (const int*)  d_in[1];
    const int*   edst    = (const int*)  d_in[2];
    const float* Wq      = (const float*)d_in[3];
    const float* bq      = (const float*)d_in[4];
    const float* Wk      = (const float*)d_in[5];
    const float* bk      = (const float*)d_in[6];
    const float* Wv      = (const float*)d_in[7];
    const float* bv      = (const float*)d_in[8];
    const float* Ws      = (const float*)d_in[9];
    const float* bs      = (const float*)d_in[10];
    const float* Wg      = (const float*)d_in[11];
    const float* bg      = (const float*)d_in[12];
    const float* ln_g    = (const float*)d_in[13];
    const float* ln_b    = (const float*)d_in[14];
    const float* prelu_a = (const float*)d_in[15];
    float* out = (float*)d_out;

    proj_kernel<<<dim3((NN + 127) / 128, 2), 256>>>(feat, Wq, bq, Wk, bk, Wv, bv, Ws, bs);
    agg_fused_kernel<<<(NN + 7) / 8, 256>>>(esrc, edst, Wg, bg, ln_g, ln_b, prelu_a, out);
}

// round 9
// speedup vs baseline: 1.4361x; 1.3035x over previous
#include <cuda_runtime.h>
#include <cstdint>

#define NN 100000
#define EE 1600000
#define FULLMASK 0xffffffffu

// Scratch: projection planes [4][N][64] (q,k,v,skip), CSR rowptr, spill.
__device__ float g_proj[(size_t)4 * NN * 64];     // 102.4 MB
__device__ float g_scores[(size_t)EE * 4];        // 25.6 MB (deg>32 only)
__device__ int   g_rowptr[NN + 1];

// ---------------------------------------------------------------------------
// K0: row_ptr[n] = lower_bound(edge_dst, n); 100k threads hide the chain.
// ---------------------------------------------------------------------------
__global__ void rowptr_kernel(const int* __restrict__ edst) {
    int n = blockIdx.x * blockDim.x + threadIdx.x;
    if (n > NN) return;
    int lo = 0, hi = EE;
    while (lo < hi) {
        int mid = (lo + hi) >> 1;
        if (edst[mid] < n) lo = mid + 1; else hi = mid;
    }
    g_rowptr[n] = lo;
}

// ---------------------------------------------------------------------------
// K1: projection GEMM, 8x8 register tiling (measured at fp32 FFMA roofline).
// ---------------------------------------------------------------------------
__global__ void __launch_bounds__(256) proj_kernel(
    const float* __restrict__ feat,
    const float* __restrict__ Wq, const float* __restrict__ bq,
    const float* __restrict__ Wk, const float* __restrict__ bk,
    const float* __restrict__ Wv, const float* __restrict__ bv,
    const float* __restrict__ Ws, const float* __restrict__ bs)
{
    __shared__ float a_t[32][132];   // [k][row], pad 132 keeps float4 aligned
    __shared__ float b_t[32][128];   // [k][col]  (col<64 -> plane A, else B)

    const int tid = threadIdx.x;
    const int rbase = blockIdx.x * 128;
    const int pp = blockIdx.y;                       // 0:{q,k} 1:{v,s}
    const float* WA = pp ? Wv : Wq;
    const float* WB = pp ? Ws : Wk;
    const float* bA = pp ? bv : bq;
    const float* bB = pp ? bs : bk;

    const int tx = tid & 15, ty = tid >> 4;
    const int col0 = tx * 8;
    const int row0 = ty * 8;

    float acc[8][8];
    {
        const float* bb = (col0 < 64) ? bA : bB;
        const int c0 = col0 & 63;
#pragma unroll
        for (int j = 0; j < 8; j++) {
            const float b = bb[c0 + j];
#pragma unroll
            for (int i = 0; i < 8; i++) acc[i][j] = b;
        }
    }

    for (int kb = 0; kb < 64; kb += 32) {
        __syncthreads();
#pragma unroll
        for (int p = 0; p < 16; p++) {
            const int idx = p * 256 + tid;
            const int row = idx >> 5, k = idx & 31;
            const int grow = rbase + row;
            a_t[k][row] = (grow < NN) ? feat[(size_t)grow * 64 + kb + k] : 0.f;
        }
#pragma unroll
        for (int p = 0; p < 16; p++) {
            const int idx = p * 256 + tid;
            const int k = idx >> 7, c = idx & 127;
            const float* W = (c < 64) ? WA : WB;
            b_t[k][c] = W[(size_t)(kb + k) * 64 + (c & 63)];
        }
        __syncthreads();

#pragma unroll
        for (int k = 0; k < 32; k++) {
            float a[8], b[8];
            *(float4*)&a[0] = *(const float4*)&a_t[k][row0];
            *(float4*)&a[4] = *(const float4*)&a_t[k][row0 + 4];
            *(float4*)&b[0] = *(const float4*)&b_t[k][col0];
            *(float4*)&b[4] = *(const float4*)&b_t[k][col0 + 4];
#pragma unroll
            for (int i = 0; i < 8; i++)
#pragma unroll
                for (int j = 0; j < 8; j++)
                    acc[i][j] += a[i] * b[j];
        }
    }

    const int plane = pp * 2 + (col0 >= 64);
    float* out = g_proj + (size_t)plane * NN * 64 + (col0 & 63);
#pragma unroll
    for (int i = 0; i < 8; i++) {
        const int grow = rbase + row0 + i;
        if (grow < NN) {
            float* o = out + (size_t)grow * 64;
            *(float4*)o       = make_float4(acc[i][0], acc[i][1], acc[i][2], acc[i][3]);
            *(float4*)(o + 4) = make_float4(acc[i][4], acc[i][5], acc[i][6], acc[i][7]);
        }
    }
}

// ---------------------------------------------------------------------------
// K2: one warp per dst node, rowptr precomputed.
// Phase 1: 4 lanes/edge compute head dots (coalesced q gathers) -> smem scores.
// Warp softmax. Phase 2: 2 edge-groups x 16 lanes, lane owns 4 dims -> one
// LDG.128 + 4 FFMA per edge per lane-group; iterations independent (high MLP).
// Recombine via shfl_xor(16) + smem (ks buffer reused). Epilogue: gate/LN/PReLU.
// ---------------------------------------------------------------------------
__global__ void __launch_bounds__(256) agg_fused_kernel(
    const int* __restrict__ esrc,
    const float* __restrict__ Wg, const float* __restrict__ bg,
    const float* __restrict__ ln_g, const float* __restrict__ ln_b,
    const float* __restrict__ prelu_a,
    float* __restrict__ out)
{
    __shared__ float  ks[8][64];     // k row, later reused as agg buffer
    __shared__ float4 wts[8][33];    // scores -> normalized weights (+pad slot)
    __shared__ int    srcs[8][33];

    const int wip  = threadIdx.x >> 5;
    const int lane = threadIdx.x & 31;
    const int node = blockIdx.x * 8 + wip;
    if (node >= NN) return;

    const int beg = g_rowptr[node];
    const int end = g_rowptr[node + 1];
    const int deg = end - beg;

    const float* qplane = g_proj;
    const float* kplane = g_proj + (size_t)1 * NN * 64;
    const float* vplane = g_proj + (size_t)2 * NN * 64;
    const float* splane = g_proj + (size_t)3 * NN * 64;

    // prefetch skip row (latency hides under phases 1-2)
    const float sk0 = splane[(size_t)node * 64 + lane];
    const float sk1 = splane[(size_t)node * 64 + lane + 32];

    // stage k[node]
    ks[wip][lane]      = kplane[(size_t)node * 64 + lane];
    ks[wip][lane + 32] = kplane[(size_t)node * 64 + lane + 32];
    __syncwarp();

    float inv[4];
    float acc0, acc1;

    if (deg <= 32) {
        // ---- phase 1: 4 lanes per edge ----
        const int h = lane & 3;
        const float4* kr = (const float4*)(ks[wip] + h * 16);
        const float4 k0 = kr[0], k1 = kr[1], k2 = kr[2], k3 = kr[3];
        const int nIter = (deg + 7) >> 3;
        for (int it = 0; it < nIter; it++) {
            const int eidx = it * 8 + (lane >> 2);
            if (eidx < deg) {
                const int src = esrc[beg + eidx];
                const float4* qr = (const float4*)(qplane + (size_t)src * 64 + h * 16);
                const float4 q0 = qr[0], q1 = qr[1], q2 = qr[2], q3 = qr[3];
                float d = q0.x*k0.x + q0.y*k0.y + q0.z*k0.z + q0.w*k0.w
                        + q1.x*k1.x + q1.y*k1.y + q1.z*k1.z + q1.w*k1.w
                        + q2.x*k2.x + q2.y*k2.y + q2.z*k2.z + q2.w*k2.w
                        + q3.x*k3.x + q3.y*k3.y + q3.z*k3.z + q3.w*k3.w;
                ((float*)wts[wip])[eidx * 4 + h] = d * 0.25f;
                if (h == 0) srcs[wip][eidx] = src;
            }
        }
        __syncwarp();

        // ---- softmax per head ----
        const bool valid = (lane < deg);
        float4 sc = valid ? wts[wip][lane]
                          : make_float4(-3e38f, -3e38f, -3e38f, -3e38f);
        float m0 = sc.x, m1 = sc.y, m2 = sc.z, m3 = sc.w;
#pragma unroll
        for (int off = 16; off; off >>= 1) {
            m0 = fmaxf(m0, __shfl_xor_sync(FULLMASK, m0, off));
            m1 = fmaxf(m1, __shfl_xor_sync(FULLMASK, m1, off));
            m2 = fmaxf(m2, __shfl_xor_sync(FULLMASK, m2, off));
            m3 = fmaxf(m3, __shfl_xor_sync(FULLMASK, m3, off));
        }
        float w0 = valid ? __expf(sc.x - m0) : 0.f;
        float w1 = valid ? __expf(sc.y - m1) : 0.f;
        float w2 = valid ? __expf(sc.z - m2) : 0.f;
        float w3 = valid ? __expf(sc.w - m3) : 0.f;
        float s0 = w0, s1 = w1, s2 = w2, s3 = w3;
#pragma unroll
        for (int off = 16; off; off >>= 1) {
            s0 += __shfl_xor_sync(FULLMASK, s0, off);
            s1 += __shfl_xor_sync(FULLMASK, s1, off);
            s2 += __shfl_xor_sync(FULLMASK, s2, off);
            s3 += __shfl_xor_sync(FULLMASK, s3, off);
        }
        const float i0 = (s0 > 0.f) ? 1.f / s0 : 0.f;
        const float i1 = (s1 > 0.f) ? 1.f / s1 : 0.f;
        const float i2 = (s2 > 0.f) ? 1.f / s2 : 0.f;
        const float i3 = (s3 > 0.f) ? 1.f / s3 : 0.f;
        if (valid)
            wts[wip][lane] = make_float4(w0 * i0, w1 * i1, w2 * i2, w3 * i3);
        // pad slot so odd degrees need no branch in phase 2
        if (lane == 0 && deg > 0) {
            wts[wip][deg]  = make_float4(0.f, 0.f, 0.f, 0.f);
            srcs[wip][deg] = srcs[wip][0];
        }
        __syncwarp();

        // ---- phase 2: 2 edge-groups x 16 lanes, 4 dims/lane ----
        const int grp  = lane >> 4;        // which edge of the pair
        const int l16  = lane & 15;        // dim group: dims 4*l16..4*l16+3
        const int hsel = l16 >> 2;         // head of those dims
        float4 av = make_float4(0.f, 0.f, 0.f, 0.f);
        const int nIt = (deg + 1) >> 1;
        for (int it = 0; it < nIt; it++) {
            const int j = it * 2 + grp;    // may hit padded slot
            const int src = srcs[wip][j];
            const float w = ((const float*)&wts[wip][j])[hsel];
            const float4 v = *(const float4*)(vplane + (size_t)src * 64 + l16 * 4);
            av.x += w * v.x; av.y += w * v.y; av.z += w * v.z; av.w += w * v.w;
        }
        av.x += __shfl_xor_sync(FULLMASK, av.x, 16);
        av.y += __shfl_xor_sync(FULLMASK, av.y, 16);
        av.z += __shfl_xor_sync(FULLMASK, av.z, 16);
        av.w += __shfl_xor_sync(FULLMASK, av.w, 16);
        __syncwarp();                      // ks reads (phase 1) done
        if (lane < 16) *(float4*)(ks[wip] + l16 * 4) = av;
        __syncwarp();
        acc0 = ks[wip][lane];
        acc1 = ks[wip][lane + 32];
    } else {
        // ---- slow path (rare): chunked through g_scores ----
        const float4* kf = (const float4*)ks[wip];
        float mloc[4] = {-3e38f, -3e38f, -3e38f, -3e38f};
        for (int c = beg; c < end; c += 32) {
            const int e = c + lane;
            if (e < end) {
                const int src = esrc[e];
                const float4* qr = (const float4*)(qplane + (size_t)src * 64);
                float a[4] = {0.f, 0.f, 0.f, 0.f};
#pragma unroll
                for (int i = 0; i < 16; i++) {
                    float4 qv = qr[i], kv = kf[i];
                    a[i >> 2] += qv.x * kv.x + qv.y * kv.y + qv.z * kv.z + qv.w * kv.w;
                }
                float4 scv = make_float4(a[0] * 0.25f, a[1] * 0.25f, a[2] * 0.25f, a[3] * 0.25f);
                *(float4*)(g_scores + (size_t)e * 4) = scv;
                mloc[0] = fmaxf(mloc[0], scv.x); mloc[1] = fmaxf(mloc[1], scv.y);
                mloc[2] = fmaxf(mloc[2], scv.z); mloc[3] = fmaxf(mloc[3], scv.w);
            }
        }
#pragma unroll
        for (int off = 16; off; off >>= 1)
#pragma unroll
            for (int h = 0; h < 4; h++)
                mloc[h] = fmaxf(mloc[h], __shfl_xor_sync(FULLMASK, mloc[h], off));
        float sloc[4] = {0.f, 0.f, 0.f, 0.f};
        for (int c = beg; c < end; c += 32) {
            const int e = c + lane;
            if (e < end) {
                float4 scv = *(const float4*)(g_scores + (size_t)e * 4);
                float4 wv = make_float4(__expf(scv.x - mloc[0]), __expf(scv.y - mloc[1]),
                                        __expf(scv.z - mloc[2]), __expf(scv.w - mloc[3]));
                *(float4*)(g_scores + (size_t)e * 4) = wv;
                sloc[0] += wv.x; sloc[1] += wv.y; sloc[2] += wv.z; sloc[3] += wv.w;
            }
        }
#pragma unroll
        for (int off = 16; off; off >>= 1)
#pragma unroll
            for (int h = 0; h < 4; h++)
                sloc[h] += __shfl_xor_sync(FULLMASK, sloc[h], off);
#pragma unroll
        for (int h = 0; h < 4; h++)
            inv[h] = (sloc[h] > 0.f) ? 1.f / sloc[h] : 0.f;

        const bool lowh = (lane < 16);
        acc0 = 0.f; acc1 = 0.f;
        for (int c = beg; c < end; c += 32) {
            const int e = c + lane;
            if (e < end) {
                float4 wv = *(const float4*)(g_scores + (size_t)e * 4);
                wts[wip][lane] = make_float4(wv.x * inv[0], wv.y * inv[1],
                                             wv.z * inv[2], wv.w * inv[3]);
            }
            __syncwarp();
            const int cnt = min(32, end - c);
            for (int j = 0; j < cnt; j++) {
                const float4 wt = wts[wip][j];
                const int src = esrc[c + j];
                const float* vr = vplane + (size_t)src * 64;
                const float wA = lowh ? wt.x : wt.y;
                const float wB = lowh ? wt.z : wt.w;
                acc0 += wA * vr[lane];
                acc1 += wB * vr[lane + 32];
            }
            __syncwarp();
        }
    }

    // ---- gated skip ----
    float gp = sk0 * Wg[lane]      + acc0 * Wg[64 + lane] + (sk0 - acc0) * Wg[128 + lane]
             + sk1 * Wg[lane + 32] + acc1 * Wg[96 + lane] + (sk1 - acc1) * Wg[160 + lane];
#pragma unroll
    for (int off = 16; off; off >>= 1) gp += __shfl_xor_sync(FULLMASK, gp, off);
    const float gate = 1.f / (1.f + __expf(-(gp + bg[0])));
    const float r0 = gate * sk0 + (1.f - gate) * acc0;
    const float r1 = gate * sk1 + (1.f - gate) * acc1;

    // ---- LayerNorm + PReLU ----
    float sum = r0 + r1, sq = r0 * r0 + r1 * r1;
#pragma unroll
    for (int off = 16; off; off >>= 1) {
        sum += __shfl_xor_sync(FULLMASK, sum, off);
        sq  += __shfl_xor_sync(FULLMASK, sq,  off);
    }
    const float mu = sum * (1.f / 64.f);
    const float var = sq * (1.f / 64.f) - mu * mu;
    const float rstd = rsqrtf(var + 1e-5f);
    const float a = prelu_a[0];

    float o0 = (r0 - mu) * rstd * ln_g[lane]      + ln_b[lane];
    float o1 = (r1 - mu) * rstd * ln_g[lane + 32] + ln_b[lane + 32];
    o0 = (o0 >= 0.f) ? o0 : a * o0;
    o1 = (o1 >= 0.f) ? o1 : a * o1;
    out[(size_t)node * 64 + lane]      = o0;
    out[(size_t)node * 64 + lane + 32] = o1;
}

// ---------------------------------------------------------------------------
extern "C" void kernel_launch(void* const* d_in, const int* in_sizes, int n_in,
                              void* d_out, int out_size)
{
    const float* feat    = (const float*)d_in[0];
    const int*   esrc    = (const int*)  d_in[1];
    const int*   edst    = (const int*)  d_in[2];
    const float* Wq      = (const float*)d_in[3];
    const float* bq      = (const float*)d_in[4];
    const float* Wk      = (const float*)d_in[5];
    const float* bk      = (const float*)d_in[6];
    const float* Wv      = (const float*)d_in[7];
    const float* bv      = (const float*)d_in[8];
    const float* Ws      = (const float*)d_in[9];
    const float* bs      = (const float*)d_in[10];
    const float* Wg      = (const float*)d_in[11];
    const float* bg      = (const float*)d_in[12];
    const float* ln_g    = (const float*)d_in[13];
    const float* ln_b    = (const float*)d_in[14];
    const float* prelu_a = (const float*)d_in[15];
    float* out = (float*)d_out;

    rowptr_kernel<<<(NN + 1 + 255) / 256, 256>>>(edst);
    proj_kernel<<<dim3((NN + 127) / 128, 2), 256>>>(feat, Wq, bq, Wk, bk, Wv, bv, Ws, bs);
    agg_fused_kernel<<<(NN + 7) / 8, 256>>>(esrc, Wg, bg, ln_g, ln_b, prelu_a, out);
}

// round 10
// speedup vs baseline: 1.4854x; 1.0343x over previous
#include <cuda_runtime.h>
#include <cstdint>

#define NN 100000
#define EE 1600000
#define FULLMASK 0xffffffffu

// Scratch: projection planes [4][N][64] (q,k,v,skip), CSR rowptr, spill.
__device__ float g_proj[(size_t)4 * NN * 64];     // 102.4 MB
__device__ float g_scores[(size_t)EE * 4];        // 25.6 MB (deg>32 only)
__device__ int   g_rowptr[NN + 1];

// packed fp32x2 helpers (FFMA2 is PTX-only; ptxas never auto-fuses)
__device__ __forceinline__ void ffma2(unsigned long long& d,
                                      unsigned long long a,
                                      unsigned long long b) {
    asm("fma.rn.f32x2 %0, %1, %2, %0;" : "+l"(d) : "l"(a), "l"(b));
}
__device__ __forceinline__ unsigned long long pack2(float lo, float hi) {
    unsigned long long r;
    asm("mov.b64 %0, {%1, %2};" : "=l"(r) : "f"(lo), "f"(hi));
    return r;
}
__device__ __forceinline__ void unpack2(unsigned long long p, float& lo, float& hi) {
    asm("mov.b64 {%0, %1}, %2;" : "=f"(lo), "=f"(hi) : "l"(p));
}

// ---------------------------------------------------------------------------
// K0: row_ptr[n] = lower_bound(edge_dst, n); 100k threads hide the chain.
// ---------------------------------------------------------------------------
__global__ void rowptr_kernel(const int* __restrict__ edst) {
    int n = blockIdx.x * blockDim.x + threadIdx.x;
    if (n > NN) return;
    int lo = 0, hi = EE;
    while (lo < hi) {
        int mid = (lo + hi) >> 1;
        if (edst[mid] < n) lo = mid + 1; else hi = mid;
    }
    g_rowptr[n] = lo;
}

// ---------------------------------------------------------------------------
// K1: projection GEMM, 8x8 tiling with packed FFMA2 (row pairs).
// acc2[p][j] holds (row 2p, row 2p+1) for col j. a-pairs come straight from
// the float4 smem loads (rows are adjacent); b is broadcast-packed per k.
// ---------------------------------------------------------------------------
__global__ void __launch_bounds__(256) proj_kernel(
    const float* __restrict__ feat,
    const float* __restrict__ Wq, const float* __restrict__ bq,
    const float* __restrict__ Wk, const float* __restrict__ bk,
    const float* __restrict__ Wv, const float* __restrict__ bv,
    const float* __restrict__ Ws, const float* __restrict__ bs)
{
    __shared__ float a_t[32][132];   // [k][row], pad 132 keeps float4 aligned
    __shared__ float b_t[32][128];   // [k][col]

    const int tid = threadIdx.x;
    const int rbase = blockIdx.x * 128;
    const int pp = blockIdx.y;                       // 0:{q,k} 1:{v,s}
    const float* WA = pp ? Wv : Wq;
    const float* WB = pp ? Ws : Wk;
    const float* bA = pp ? bv : bq;
    const float* bB = pp ? bs : bk;

    const int tx = tid & 15, ty = tid >> 4;
    const int col0 = tx * 8;
    const int row0 = ty * 8;

    unsigned long long acc2[4][8];   // [row-pair][col]
    {
        const float* bb = (col0 < 64) ? bA : bB;
        const int c0 = col0 & 63;
#pragma unroll
        for (int j = 0; j < 8; j++) {
            const unsigned long long b2 = pack2(bb[c0 + j], bb[c0 + j]);
#pragma unroll
            for (int p = 0; p < 4; p++) acc2[p][j] = b2;
        }
        // acc2 currently holds bias in both halves; subtract one copy at end?
        // No: bias must appear once per element. Initialize to bias is correct:
        // each half is one output element's accumulator seeded with its bias.
    }

    for (int kb = 0; kb < 64; kb += 32) {
        __syncthreads();
#pragma unroll
        for (int p = 0; p < 16; p++) {
            const int idx = p * 256 + tid;
            const int row = idx >> 5, k = idx & 31;
            const int grow = rbase + row;
            a_t[k][row] = (grow < NN) ? feat[(size_t)grow * 64 + kb + k] : 0.f;
        }
#pragma unroll
        for (int p = 0; p < 16; p++) {
            const int idx = p * 256 + tid;
            const int k = idx >> 7, c = idx & 127;
            const float* W = (c < 64) ? WA : WB;
            b_t[k][c] = W[(size_t)(kb + k) * 64 + (c & 63)];
        }
        __syncthreads();

#pragma unroll
        for (int k = 0; k < 32; k++) {
            // a row-pairs: rows row0..row0+7 -> 4 packed pairs via 2 LDS.128
            const ulonglong2 ap0 = *(const ulonglong2*)&a_t[k][row0];
            const ulonglong2 ap1 = *(const ulonglong2*)&a_t[k][row0 + 4];
            const unsigned long long ap[4] = {ap0.x, ap0.y, ap1.x, ap1.y};
            float b[8];
            *(float4*)&b[0] = *(const float4*)&b_t[k][col0];
            *(float4*)&b[4] = *(const float4*)&b_t[k][col0 + 4];
            unsigned long long b2[8];
#pragma unroll
            for (int j = 0; j < 8; j++) b2[j] = pack2(b[j], b[j]);
#pragma unroll
            for (int p = 0; p < 4; p++)
#pragma unroll
                for (int j = 0; j < 8; j++)
                    ffma2(acc2[p][j], ap[p], b2[j]);
        }
    }

    const int plane = pp * 2 + (col0 >= 64);
    float* out = g_proj + (size_t)plane * NN * 64 + (col0 & 63);
#pragma unroll
    for (int p = 0; p < 4; p++) {
        float lo[8], hi[8];
#pragma unroll
        for (int j = 0; j < 8; j++) unpack2(acc2[p][j], lo[j], hi[j]);
        const int grow0 = rbase + row0 + 2 * p;
        if (grow0 < NN) {
            float* o = out + (size_t)grow0 * 64;
            *(float4*)o       = make_float4(lo[0], lo[1], lo[2], lo[3]);
            *(float4*)(o + 4) = make_float4(lo[4], lo[5], lo[6], lo[7]);
        }
        if (grow0 + 1 < NN) {
            float* o = out + (size_t)(grow0 + 1) * 64;
            *(float4*)o       = make_float4(hi[0], hi[1], hi[2], hi[3]);
            *(float4*)(o + 4) = make_float4(hi[4], hi[5], hi[6], hi[7]);
        }
    }
}

// ---------------------------------------------------------------------------
// K2: one warp per dst node. Phase 1: 4 lanes/edge -> smem scores. Warp
// softmax. Phase 2: 2 edge-groups x 16 lanes, unrolled x2 (4 edges/iter,
// 2 independent LDG.128 per lane in flight). Epilogue: gate/LN/PReLU.
// ---------------------------------------------------------------------------
__global__ void __launch_bounds__(256) agg_fused_kernel(
    const int* __restrict__ esrc,
    const float* __restrict__ Wg, const float* __restrict__ bg,
    const float* __restrict__ ln_g, const float* __restrict__ ln_b,
    const float* __restrict__ prelu_a,
    float* __restrict__ out)
{
    __shared__ float  ks[8][64];     // k row, later reused as agg buffer
    __shared__ float4 wts[8][36];    // scores -> weights (+3 pad slots)
    __shared__ int    srcs[8][36];

    const int wip  = threadIdx.x >> 5;
    const int lane = threadIdx.x & 31;
    const int node = blockIdx.x * 8 + wip;
    if (node >= NN) return;

    const int beg = g_rowptr[node];
    const int end = g_rowptr[node + 1];
    const int deg = end - beg;

    const float* qplane = g_proj;
    const float* kplane = g_proj + (size_t)1 * NN * 64;
    const float* vplane = g_proj + (size_t)2 * NN * 64;
    const float* splane = g_proj + (size_t)3 * NN * 64;

    // prefetch skip row (latency hides under phases 1-2)
    const float sk0 = splane[(size_t)node * 64 + lane];
    const float sk1 = splane[(size_t)node * 64 + lane + 32];

    // stage k[node]
    ks[wip][lane]      = kplane[(size_t)node * 64 + lane];
    ks[wip][lane + 32] = kplane[(size_t)node * 64 + lane + 32];
    __syncwarp();

    float inv[4];
    float acc0, acc1;

    if (deg <= 32) {
        // ---- phase 1: 4 lanes per edge ----
        const int h = lane & 3;
        const float4* kr = (const float4*)(ks[wip] + h * 16);
        const float4 k0 = kr[0], k1 = kr[1], k2 = kr[2], k3 = kr[3];
        const int nIter = (deg + 7) >> 3;
        for (int it = 0; it < nIter; it++) {
            const int eidx = it * 8 + (lane >> 2);
            if (eidx < deg) {
                const int src = esrc[beg + eidx];
                const float4* qr = (const float4*)(qplane + (size_t)src * 64 + h * 16);
                const float4 q0 = qr[0], q1 = qr[1], q2 = qr[2], q3 = qr[3];
                float d = q0.x*k0.x + q0.y*k0.y + q0.z*k0.z + q0.w*k0.w
                        + q1.x*k1.x + q1.y*k1.y + q1.z*k1.z + q1.w*k1.w
                        + q2.x*k2.x + q2.y*k2.y + q2.z*k2.z + q2.w*k2.w
                        + q3.x*k3.x + q3.y*k3.y + q3.z*k3.z + q3.w*k3.w;
                ((float*)wts[wip])[eidx * 4 + h] = d * 0.25f;
                if (h == 0) srcs[wip][eidx] = src;
            }
        }
        __syncwarp();

        // ---- softmax per head ----
        const bool valid = (lane < deg);
        float4 sc = valid ? wts[wip][lane]
                          : make_float4(-3e38f, -3e38f, -3e38f, -3e38f);
        float m0 = sc.x, m1 = sc.y, m2 = sc.z, m3 = sc.w;
#pragma unroll
        for (int off = 16; off; off >>= 1) {
            m0 = fmaxf(m0, __shfl_xor_sync(FULLMASK, m0, off));
            m1 = fmaxf(m1, __shfl_xor_sync(FULLMASK, m1, off));
            m2 = fmaxf(m2, __shfl_xor_sync(FULLMASK, m2, off));
            m3 = fmaxf(m3, __shfl_xor_sync(FULLMASK, m3, off));
        }
        float w0 = valid ? __expf(sc.x - m0) : 0.f;
        float w1 = valid ? __expf(sc.y - m1) : 0.f;
        float w2 = valid ? __expf(sc.z - m2) : 0.f;
        float w3 = valid ? __expf(sc.w - m3) : 0.f;
        float s0 = w0, s1 = w1, s2 = w2, s3 = w3;
#pragma unroll
        for (int off = 16; off; off >>= 1) {
            s0 += __shfl_xor_sync(FULLMASK, s0, off);
            s1 += __shfl_xor_sync(FULLMASK, s1, off);
            s2 += __shfl_xor_sync(FULLMASK, s2, off);
            s3 += __shfl_xor_sync(FULLMASK, s3, off);
        }
        const float i0 = (s0 > 0.f) ? 1.f / s0 : 0.f;
        const float i1 = (s1 > 0.f) ? 1.f / s1 : 0.f;
        const float i2 = (s2 > 0.f) ? 1.f / s2 : 0.f;
        const float i3 = (s3 > 0.f) ? 1.f / s3 : 0.f;
        if (valid)
            wts[wip][lane] = make_float4(w0 * i0, w1 * i1, w2 * i2, w3 * i3);
        // 3 pad slots so phase 2 can run in unguarded groups of 4
        if (lane < 3 && deg > 0) {
            wts[wip][deg + lane]  = make_float4(0.f, 0.f, 0.f, 0.f);
            srcs[wip][deg + lane] = srcs[wip][0];
        }
        __syncwarp();

        // ---- phase 2: 2 edge-groups x 16 lanes, unrolled x2 ----
        const int grp  = lane >> 4;        // edge-group
        const int l16  = lane & 15;        // dims 4*l16..4*l16+3
        const int hsel = l16 >> 2;         // head of those dims
        float4 av = make_float4(0.f, 0.f, 0.f, 0.f);
        const int nIt = (deg + 3) >> 2;
        for (int it = 0; it < nIt; it++) {
            const int j0 = it * 4 + grp;
            const int j1 = j0 + 2;
            const int srcA = srcs[wip][j0];
            const int srcB = srcs[wip][j1];
            const float wA = ((const float*)&wts[wip][j0])[hsel];
            const float wB = ((const float*)&wts[wip][j1])[hsel];
            const float4 vA = *(const float4*)(vplane + (size_t)srcA * 64 + l16 * 4);
            const float4 vB = *(const float4*)(vplane + (size_t)srcB * 64 + l16 * 4);
            av.x += wA * vA.x; av.y += wA * vA.y; av.z += wA * vA.z; av.w += wA * vA.w;
            av.x += wB * vB.x; av.y += wB * vB.y; av.z += wB * vB.z; av.w += wB * vB.w;
        }
        av.x += __shfl_xor_sync(FULLMASK, av.x, 16);
        av.y += __shfl_xor_sync(FULLMASK, av.y, 16);
        av.z += __shfl_xor_sync(FULLMASK, av.z, 16);
        av.w += __shfl_xor_sync(FULLMASK, av.w, 16);
        __syncwarp();
        if (lane < 16) *(float4*)(ks[wip] + l16 * 4) = av;
        __syncwarp();
        acc0 = ks[wip][lane];
        acc1 = ks[wip][lane + 32];
    } else {
        // ---- slow path (rare): chunked through g_scores ----
        const float4* kf = (const float4*)ks[wip];
        float mloc[4] = {-3e38f, -3e38f, -3e38f, -3e38f};
        for (int c = beg; c < end; c += 32) {
            const int e = c + lane;
            if (e < end) {
                const int src = esrc[e];
                const float4* qr = (const float4*)(qplane + (size_t)src * 64);
                float a[4] = {0.f, 0.f, 0.f, 0.f};
#pragma unroll
                for (int i = 0; i < 16; i++) {
                    float4 qv = qr[i], kv = kf[i];
                    a[i >> 2] += qv.x * kv.x + qv.y * kv.y + qv.z * kv.z + qv.w * kv.w;
                }
                float4 scv = make_float4(a[0] * 0.25f, a[1] * 0.25f, a[2] * 0.25f, a[3] * 0.25f);
                *(float4*)(g_scores + (size_t)e * 4) = scv;
                mloc[0] = fmaxf(mloc[0], scv.x); mloc[1] = fmaxf(mloc[1], scv.y);
                mloc[2] = fmaxf(mloc[2], scv.z); mloc[3] = fmaxf(mloc[3], scv.w);
            }
        }
#pragma unroll
        for (int off = 16; off; off >>= 1)
#pragma unroll
            for (int h = 0; h < 4; h++)
                mloc[h] = fmaxf(mloc[h], __shfl_xor_sync(FULLMASK, mloc[h], off));
        float sloc[4] = {0.f, 0.f, 0.f, 0.f};
        for (int c = beg; c < end; c += 32) {
            const int e = c + lane;
            if (e < end) {
                float4 scv = *(const float4*)(g_scores + (size_t)e * 4);
                float4 wv = make_float4(__expf(scv.x - mloc[0]), __expf(scv.y - mloc[1]),
                                        __expf(scv.z - mloc[2]), __expf(scv.w - mloc[3]));
                *(float4*)(g_scores + (size_t)e * 4) = wv;
                sloc[0] += wv.x; sloc[1] += wv.y; sloc[2] += wv.z; sloc[3] += wv.w;
            }
        }
#pragma unroll
        for (int off = 16; off; off >>= 1)
#pragma unroll
            for (int h = 0; h < 4; h++)
                sloc[h] += __shfl_xor_sync(FULLMASK, sloc[h], off);
#pragma unroll
        for (int h = 0; h < 4; h++)
            inv[h] = (sloc[h] > 0.f) ? 1.f / sloc[h] : 0.f;

        const bool lowh = (lane < 16);
        acc0 = 0.f; acc1 = 0.f;
        for (int c = beg; c < end; c += 32) {
            const int e = c + lane;
            if (e < end) {
                float4 wv = *(const float4*)(g_scores + (size_t)e * 4);
                wts[wip][lane] = make_float4(wv.x * inv[0], wv.y * inv[1],
                                             wv.z * inv[2], wv.w * inv[3]);
            }
            __syncwarp();
            const int cnt = min(32, end - c);
            for (int j = 0; j < cnt; j++) {
                const float4 wt = wts[wip][j];
                const int src = esrc[c + j];
                const float* vr = vplane + (size_t)src * 64;
                const float wA = lowh ? wt.x : wt.y;
                const float wB = lowh ? wt.z : wt.w;
                acc0 += wA * vr[lane];
                acc1 += wB * vr[lane + 32];
            }
            __syncwarp();
        }
    }

    // ---- gated skip ----
    float gp = sk0 * Wg[lane]      + acc0 * Wg[64 + lane] + (sk0 - acc0) * Wg[128 + lane]
             + sk1 * Wg[lane + 32] + acc1 * Wg[96 + lane] + (sk1 - acc1) * Wg[160 + lane];
#pragma unroll
    for (int off = 16; off; off >>= 1) gp += __shfl_xor_sync(FULLMASK, gp, off);
    const float gate = 1.f / (1.f + __expf(-(gp + bg[0])));
    const float r0 = gate * sk0 + (1.f - gate) * acc0;
    const float r1 = gate * sk1 + (1.f - gate) * acc1;

    // ---- LayerNorm + PReLU ----
    float sum = r0 + r1, sq = r0 * r0 + r1 * r1;
#pragma unroll
    for (int off = 16; off; off >>= 1) {
        sum += __shfl_xor_sync(FULLMASK, sum, off);
        sq  += __shfl_xor_sync(FULLMASK, sq,  off);
    }
    const float mu = sum * (1.f / 64.f);
    const float var = sq * (1.f / 64.f) - mu * mu;
    const float rstd = rsqrtf(var + 1e-5f);
    const float a = prelu_a[0];

    float o0 = (r0 - mu) * rstd * ln_g[lane]      + ln_b[lane];
    float o1 = (r1 - mu) * rstd * ln_g[lane + 32] + ln_b[lane + 32];
    o0 = (o0 >= 0.f) ? o0 : a * o0;
    o1 = (o1 >= 0.f) ? o1 : a * o1;
    out[(size_t)node * 64 + lane]      = o0;
    out[(size_t)node * 64 + lane + 32] = o1;
}

// ---------------------------------------------------------------------------
extern "C" void kernel_launch(void* const* d_in, const int* in_sizes, int n_in,
                              void* d_out, int out_size)
{
    const float* feat    = (const float*)d_in[0];
    const int*   esrc    = (const int*)  d_in[1];
    const int*   edst    = (const int*)  d_in[2];
    const float* Wq      = (const float*)d_in[3];
    const float* bq      = (const float*)d_in[4];
    const float* Wk      = (const float*)d_in[5];
    const float* bk      = (const float*)d_in[6];
    const float* Wv      = (const float*)d_in[7];
    const float* bv      = (const float*)d_in[8];
    const float* Ws      = (const float*)d_in[9];
    const float* bs      = (const float*)d_in[10];
    const float* Wg      = (const float*)d_in[11];
    const float* bg      = (const float*)d_in[12];
    const float* ln_g    = (const float*)d_in[13];
    const float* ln_b    = (const float*)d_in[14];
    const float* prelu_a = (const float*)d_in[15];
    float* out = (float*)d_out;

    rowptr_kernel<<<(NN + 1 + 255) / 256, 256>>>(edst);
    proj_kernel<<<dim3((NN + 127) / 128, 2), 256>>>(feat, Wq, bq, Wk, bk, Wv, bv, Ws, bs);
    agg_fused_kernel<<<(NN + 7) / 8, 256>>>(esrc, Wg, bg, ln_g, ln_b, prelu_a, out);
}